// round 1
// baseline (speedup 1.0000x reference)
#include <cuda_runtime.h>

// SRLEmbeddings: B=16,S=32,L=128,D=768,A=6,M=10
//
// Inputs (metadata order):
//   0: sentence_ids             [B,S,L]     int32
//   1: sentence_attention_masks [B,S,L]     int32
//   2: sentence_embeddings      [B,S,L,D]   float32
//   3: predicate_ids            [B,S,A,M]   int32
//   4: arg0_ids                 [B,S,A,M]   int32
//   5: arg1_ids                 [B,S,A,M]   int32
// Output (float32, concatenated):
//   sentence_avg [B,S,D] | predicate [B,S,A,D] | arg0 [B,S,A,D] | arg1 [B,S,A,D]

#define Bc 16
#define Sc 32
#define Lc 128
#define Dc 768
#define Ac 6
#define Mc 10
#define NSLOT 18   // 3 arg types * A

__global__ __launch_bounds__(256, 4)
void srl_kernel(const int*   __restrict__ sid_g,
                const int*   __restrict__ mask_g,
                const float* __restrict__ emb_g,
                const int*   __restrict__ pred_g,
                const int*   __restrict__ arg0_g,
                const int*   __restrict__ arg1_g,
                float*       __restrict__ out)
{
    __shared__ int      sid[Lc];
    __shared__ unsigned mbits[4];
    __shared__ float    minv;
    __shared__ unsigned sbits[NSLOT][4];
    __shared__ float    sinv[NSLOT];
    __shared__ int      svalid[NSLOT];

    const int bs   = blockIdx.x;          // 0..511 = b*S+s
    const int tid  = threadIdx.x;
    const int wid  = tid >> 5;
    const int lane = tid & 31;

    // ---------------- Phase 1a: load sentence ids + mask bitmap ----------------
    if (tid < Lc) sid[tid] = sid_g[bs * Lc + tid];
    if (wid < 4) {
        int l  = wid * 32 + lane;
        int mv = mask_g[bs * Lc + l];
        unsigned b = __ballot_sync(0xFFFFFFFFu, mv != 0);
        if (lane == 0) mbits[wid] = b;
    }
    __syncthreads();

    if (tid == 0) {
        int cnt = __popc(mbits[0]) + __popc(mbits[1]) + __popc(mbits[2]) + __popc(mbits[3]);
        minv = 1.0f / (float)max(cnt, 1);
    }

    // ---------------- Phase 1b: per-arg-slot token selection ----------------
    // slot = type*A + a ; type 0=predicate, 1=arg0, 2=arg1.
    for (int slot = wid; slot < NSLOT; slot += 8) {
        const int type = slot / Ac;
        const int a    = slot % Ac;
        const int* ids = (type == 0) ? pred_g : (type == 1) ? arg0_g : arg1_g;
        const int base = (bs * Ac + a) * Mc;

        int val = 0;
        float inv = 0.0f;
        unsigned b0 = 0, b1 = 0, b2 = 0, b3 = 0;

        // last m (highest) with token!=0 and >=1 match wins
        for (int m = Mc - 1; m >= 0; --m) {
            int tok = ids[base + m];
            if (tok == 0) continue;
            unsigned c0 = __ballot_sync(0xFFFFFFFFu, sid[lane]      == tok);
            unsigned c1 = __ballot_sync(0xFFFFFFFFu, sid[lane + 32] == tok);
            unsigned c2 = __ballot_sync(0xFFFFFFFFu, sid[lane + 64] == tok);
            unsigned c3 = __ballot_sync(0xFFFFFFFFu, sid[lane + 96] == tok);
            int cnt = __popc(c0) + __popc(c1) + __popc(c2) + __popc(c3);
            if (cnt > 0) {
                val = 1;
                inv = 1.0f / (float)cnt;
                b0 = c0; b1 = c1; b2 = c2; b3 = c3;
                break;
            }
        }
        if (lane == 0) {
            svalid[slot]  = val;
            sinv[slot]    = inv;
            sbits[slot][0] = b0; sbits[slot][1] = b1;
            sbits[slot][2] = b2; sbits[slot][3] = b3;
        }
    }
    __syncthreads();

    // ---------------- Phase 2: weighted row sums over D ----------------
    // Each thread owns 3 columns: d, d+256, d+512 (stride-256 => coalesced).
    const float* embb = emb_g + (size_t)bs * Lc * Dc;
    const int d0 = tid, d1 = tid + 256, d2 = tid + 512;

    // 2a: masked mean
    {
        float s0 = 0.f, s1 = 0.f, s2 = 0.f;
        #pragma unroll
        for (int w = 0; w < 4; ++w) {
            unsigned bb = mbits[w];
            while (bb) {
                int l = w * 32 + __ffs(bb) - 1;
                bb &= bb - 1;
                const float* p = embb + (size_t)l * Dc;
                s0 += p[d0]; s1 += p[d1]; s2 += p[d2];
            }
        }
        float iv = minv;
        float* o = out + (size_t)bs * Dc;
        o[d0] = s0 * iv; o[d1] = s1 * iv; o[d2] = s2 * iv;
    }

    // 2b: arg slots (sparse gathers, mostly L1/L2 hits)
    const size_t OPRED = (size_t)Bc * Sc * Dc;                 // 393216
    const size_t OA    = (size_t)Bc * Sc * Ac * Dc;            // 2359296
    for (int slot = 0; slot < NSLOT; ++slot) {
        const int type = slot / Ac;
        const int a    = slot % Ac;
        size_t obase = OPRED + (size_t)type * OA + ((size_t)bs * Ac + a) * Dc;

        float s0 = 0.f, s1 = 0.f, s2 = 0.f;
        if (svalid[slot]) {
            #pragma unroll
            for (int w = 0; w < 4; ++w) {
                unsigned bb = sbits[slot][w];
                while (bb) {
                    int l = w * 32 + __ffs(bb) - 1;
                    bb &= bb - 1;
                    const float* p = embb + (size_t)l * Dc;
                    s0 += p[d0]; s1 += p[d1]; s2 += p[d2];
                }
            }
            float iv = sinv[slot];
            s0 *= iv; s1 *= iv; s2 *= iv;
        }
        out[obase + d0] = s0;
        out[obase + d1] = s1;
        out[obase + d2] = s2;
    }
}

extern "C" void kernel_launch(void* const* d_in, const int* in_sizes, int n_in,
                              void* d_out, int out_size)
{
    const int*   sid  = (const int*)  d_in[0];
    const int*   mask = (const int*)  d_in[1];
    const float* emb  = (const float*)d_in[2];
    const int*   pred = (const int*)  d_in[3];
    const int*   arg0 = (const int*)  d_in[4];
    const int*   arg1 = (const int*)  d_in[5];
    float* out = (float*)d_out;

    srl_kernel<<<Bc * Sc, 256>>>(sid, mask, emb, pred, arg0, arg1, out);
}

// round 2
// speedup vs baseline: 1.4530x; 1.4530x over previous
#include <cuda_runtime.h>

// SRLEmbeddings: B=16,S=32,L=128,D=768,A=6,M=10
// grid (512, 2): x = b*S+s, y = D-half. block 192, each thread owns 2 columns.

#define Bc 16
#define Sc 32
#define Lc 128
#define Dc 768
#define Ac 6
#define Mc 10
#define NSLOT 18       // 3 arg types * A
#define TPB 192
#define DHALF 384      // columns per CTA

__global__ __launch_bounds__(TPB, 8)
void srl_kernel(const int*   __restrict__ sid_g,
                const int*   __restrict__ mask_g,
                const float* __restrict__ emb_g,
                const int*   __restrict__ pred_g,
                const int*   __restrict__ arg0_g,
                const int*   __restrict__ arg1_g,
                float*       __restrict__ out)
{
    __shared__ int      sid[Lc];
    __shared__ unsigned mbits[4];
    __shared__ int      rows[Lc];        // ascending list of mask==1 positions
    __shared__ int      nrows;
    __shared__ float    minv;
    __shared__ unsigned sbits[NSLOT][4];
    __shared__ float    sinv[NSLOT];
    __shared__ int      svalid[NSLOT];

    const int bs   = blockIdx.x;          // 0..511
    const int tid  = threadIdx.x;
    const int wid  = tid >> 5;            // 0..5
    const int lane = tid & 31;

    // ---------- Phase 1a: sentence ids + mask bitmap ----------
    if (tid < Lc) sid[tid] = sid_g[bs * Lc + tid];
    if (wid < 4) {
        int mv = mask_g[bs * Lc + wid * 32 + lane];
        unsigned b = __ballot_sync(0xFFFFFFFFu, mv != 0);
        if (lane == 0) mbits[wid] = b;
    }
    __syncthreads();

    // ---------- Phase 1b: expand mask bitmap to index list (warps 0-3) ----------
    if (wid < 4) {
        unsigned b = mbits[wid];
        int off = 0;
        #pragma unroll
        for (int w = 0; w < 4; ++w) if (w < wid) off += __popc(mbits[w]);
        if (b & (1u << lane)) {
            int rank = __popc(b & ((1u << lane) - 1u));
            rows[off + rank] = wid * 32 + lane;
        }
    }
    if (tid == 0) {
        int cnt = __popc(mbits[0]) + __popc(mbits[1]) + __popc(mbits[2]) + __popc(mbits[3]);
        nrows = cnt;
        minv  = 1.0f / (float)max(cnt, 1);
    }

    // ---------- Phase 1c: per-arg-slot token selection (all 6 warps) ----------
    for (int slot = wid; slot < NSLOT; slot += 6) {
        const int type = slot / Ac;
        const int a    = slot % Ac;
        const int* ids = (type == 0) ? pred_g : (type == 1) ? arg0_g : arg1_g;
        const int base = (bs * Ac + a) * Mc;

        int val = 0; float inv = 0.0f;
        unsigned b0 = 0, b1 = 0, b2 = 0, b3 = 0;
        for (int m = Mc - 1; m >= 0; --m) {           // last m with a match wins
            int tok = ids[base + m];
            if (tok == 0) continue;
            unsigned c0 = __ballot_sync(0xFFFFFFFFu, sid[lane]      == tok);
            unsigned c1 = __ballot_sync(0xFFFFFFFFu, sid[lane + 32] == tok);
            unsigned c2 = __ballot_sync(0xFFFFFFFFu, sid[lane + 64] == tok);
            unsigned c3 = __ballot_sync(0xFFFFFFFFu, sid[lane + 96] == tok);
            int cnt = __popc(c0) + __popc(c1) + __popc(c2) + __popc(c3);
            if (cnt > 0) {
                val = 1; inv = 1.0f / (float)cnt;
                b0 = c0; b1 = c1; b2 = c2; b3 = c3;
                break;
            }
        }
        if (lane == 0) {
            svalid[slot] = val; sinv[slot] = inv;
            sbits[slot][0] = b0; sbits[slot][1] = b1;
            sbits[slot][2] = b2; sbits[slot][3] = b3;
        }
    }
    __syncthreads();

    // ---------- Phase 2: weighted row sums ----------
    const float* embb = emb_g + (size_t)bs * Lc * Dc;
    const int c0 = blockIdx.y * DHALF + tid;          // coalesced per warp
    const int c1 = c0 + TPB;

    // 2a: masked mean — unrolled x4 for MLP (8 loads in flight per thread)
    {
        const int n = nrows;
        float s0 = 0.f, s1 = 0.f;
        int i = 0;
        for (; i + 4 <= n; i += 4) {
            const float* p0 = embb + (size_t)rows[i]     * Dc;
            const float* p1 = embb + (size_t)rows[i + 1] * Dc;
            const float* p2 = embb + (size_t)rows[i + 2] * Dc;
            const float* p3 = embb + (size_t)rows[i + 3] * Dc;
            float a0 = p0[c0], a1 = p0[c1];
            float b0 = p1[c0], b1 = p1[c1];
            float e0 = p2[c0], e1 = p2[c1];
            float f0 = p3[c0], f1 = p3[c1];
            s0 += (a0 + b0) + (e0 + f0);
            s1 += (a1 + b1) + (e1 + f1);
        }
        for (; i < n; ++i) {
            const float* p = embb + (size_t)rows[i] * Dc;
            s0 += p[c0]; s1 += p[c1];
        }
        const float iv = minv;
        float* o = out + (size_t)bs * Dc;
        o[c0] = s0 * iv; o[c1] = s1 * iv;
    }

    // 2b: arg slots (sparse; rows usually already in L1/L2)
    const size_t OPRED = (size_t)Bc * Sc * Dc;             // 393216
    const size_t OA    = (size_t)Bc * Sc * Ac * Dc;        // 2359296
    for (int slot = 0; slot < NSLOT; ++slot) {
        const int type = slot / Ac;
        const int a    = slot % Ac;
        const size_t obase = OPRED + (size_t)type * OA + ((size_t)bs * Ac + a) * Dc;

        float s0 = 0.f, s1 = 0.f;
        if (svalid[slot]) {
            #pragma unroll
            for (int w = 0; w < 4; ++w) {
                unsigned bb = sbits[slot][w];
                while (bb) {
                    int l = w * 32 + __ffs(bb) - 1;
                    bb &= bb - 1;
                    const float* p = embb + (size_t)l * Dc;
                    s0 += p[c0]; s1 += p[c1];
                }
            }
            const float iv = sinv[slot];
            s0 *= iv; s1 *= iv;
        }
        out[obase + c0] = s0;
        out[obase + c1] = s1;
    }
}

extern "C" void kernel_launch(void* const* d_in, const int* in_sizes, int n_in,
                              void* d_out, int out_size)
{
    const int*   sid  = (const int*)  d_in[0];
    const int*   mask = (const int*)  d_in[1];
    const float* emb  = (const float*)d_in[2];
    const int*   pred = (const int*)  d_in[3];
    const int*   arg0 = (const int*)  d_in[4];
    const int*   arg1 = (const int*)  d_in[5];
    float* out = (float*)d_out;

    dim3 grid(Bc * Sc, 2);
    srl_kernel<<<grid, TPB>>>(sid, mask, emb, pred, arg0, arg1, out);
}

// round 3
// speedup vs baseline: 1.4599x; 1.0048x over previous
#include <cuda_runtime.h>

// SRLEmbeddings: B=16,S=32,L=128,D=768,A=6,M=10
// grid (512, 2): x = b*S+s, y = D-half. block 192, each thread owns 1 float2.

#define Bc 16
#define Sc 32
#define Lc 128
#define Dc 768
#define D2 384          // float2 per row
#define Ac 6
#define Mc 10
#define NSLOT 18        // 3 arg types * A
#define TPB 192
#define MAXENT (NSLOT * Lc)

__global__ __launch_bounds__(TPB, 6)
void srl_kernel(const int*   __restrict__ sid_g,
                const int*   __restrict__ mask_g,
                const float* __restrict__ emb_g,
                const int*   __restrict__ pred_g,
                const int*   __restrict__ arg0_g,
                const int*   __restrict__ arg1_g,
                float*       __restrict__ out)
{
    __shared__ int            sid[Lc];
    __shared__ unsigned       mbits[4];
    __shared__ int            rows[Lc];
    __shared__ int            nrows;
    __shared__ float          minv;
    __shared__ unsigned       sbits[NSLOT][4];
    __shared__ float          sinv[NSLOT];
    __shared__ int            svalid[NSLOT];
    __shared__ int            sofs[NSLOT];
    __shared__ int            nent_s;
    __shared__ unsigned short ent[MAXENT];   // row | (slot<<8), slot-ordered

    const int bs   = blockIdx.x;
    const int tid  = threadIdx.x;
    const int wid  = tid >> 5;               // 0..5
    const int lane = tid & 31;

    // ---------- Phase 1a: sentence ids + mask bitmap ----------
    if (tid < Lc) sid[tid] = sid_g[bs * Lc + tid];
    if (wid < 4) {
        int mv = mask_g[bs * Lc + wid * 32 + lane];
        unsigned b = __ballot_sync(0xFFFFFFFFu, mv != 0);
        if (lane == 0) mbits[wid] = b;
    }
    __syncthreads();

    // ---------- Phase 1b: expand mask bitmap to row list (warps 0-3) ----------
    if (wid < 4) {
        unsigned b = mbits[wid];
        int off = 0;
        #pragma unroll
        for (int w = 0; w < 4; ++w) if (w < wid) off += __popc(mbits[w]);
        if (b & (1u << lane)) {
            int rank = __popc(b & ((1u << lane) - 1u));
            rows[off + rank] = wid * 32 + lane;
        }
    }
    if (tid == 0) {
        int cnt = __popc(mbits[0]) + __popc(mbits[1]) + __popc(mbits[2]) + __popc(mbits[3]);
        nrows = cnt;
        minv  = 1.0f / (float)max(cnt, 1);
    }

    // ---------- Phase 1c: per-arg-slot token selection (6 warps) ----------
    for (int slot = wid; slot < NSLOT; slot += 6) {
        const int type = slot / Ac;
        const int a    = slot % Ac;
        const int* ids = (type == 0) ? pred_g : (type == 1) ? arg0_g : arg1_g;
        const int base = (bs * Ac + a) * Mc;

        int val = 0; float inv = 0.0f;
        unsigned b0 = 0, b1 = 0, b2 = 0, b3 = 0;
        for (int m = Mc - 1; m >= 0; --m) {           // last m with a match wins
            int tok = ids[base + m];
            if (tok == 0) continue;
            unsigned c0 = __ballot_sync(0xFFFFFFFFu, sid[lane]      == tok);
            unsigned c1 = __ballot_sync(0xFFFFFFFFu, sid[lane + 32] == tok);
            unsigned c2 = __ballot_sync(0xFFFFFFFFu, sid[lane + 64] == tok);
            unsigned c3 = __ballot_sync(0xFFFFFFFFu, sid[lane + 96] == tok);
            int cnt = __popc(c0) + __popc(c1) + __popc(c2) + __popc(c3);
            if (cnt > 0) {
                val = 1; inv = 1.0f / (float)cnt;
                b0 = c0; b1 = c1; b2 = c2; b3 = c3;
                break;
            }
        }
        if (lane == 0) {
            svalid[slot] = val; sinv[slot] = inv;
            sbits[slot][0] = b0; sbits[slot][1] = b1;
            sbits[slot][2] = b2; sbits[slot][3] = b3;
        }
    }
    __syncthreads();

    // ---------- Phase 1d: prefix offsets for flat entry list ----------
    if (tid == 0) {
        int run = 0;
        #pragma unroll
        for (int s = 0; s < NSLOT; ++s) {
            sofs[s] = run;
            run += __popc(sbits[s][0]) + __popc(sbits[s][1]) +
                   __popc(sbits[s][2]) + __popc(sbits[s][3]);
        }
        nent_s = run;
    }
    __syncthreads();

    // ---------- Phase 1e: expand slot bitmaps to flat entries (6 warps) ----------
    for (int slot = wid; slot < NSLOT; slot += 6) {
        int off = sofs[slot];
        #pragma unroll
        for (int w = 0; w < 4; ++w) {
            unsigned bb = sbits[slot][w];
            if (bb & (1u << lane)) {
                int rank = __popc(bb & ((1u << lane) - 1u));
                ent[off + rank] = (unsigned short)((w * 32 + lane) | (slot << 8));
            }
            off += __popc(bb);
        }
    }
    __syncthreads();

    // ---------- Phase 2: float2 streaming ----------
    const float2* emb2 = (const float2*)(emb_g + (size_t)bs * Lc * Dc);  // row stride D2
    float2* out2 = (float2*)out;
    const int c = blockIdx.y * TPB + tid;        // float2 column, coalesced

    // 2a: masked mean, unroll x8 (8 independent LDG.64 in flight)
    {
        const int n = nrows;
        float s0 = 0.f, s1 = 0.f;
        int i = 0;
        for (; i + 8 <= n; i += 8) {
            int r0 = rows[i],     r1 = rows[i + 1], r2 = rows[i + 2], r3 = rows[i + 3];
            int r4 = rows[i + 4], r5 = rows[i + 5], r6 = rows[i + 6], r7 = rows[i + 7];
            float2 v0 = emb2[(size_t)r0 * D2 + c];
            float2 v1 = emb2[(size_t)r1 * D2 + c];
            float2 v2 = emb2[(size_t)r2 * D2 + c];
            float2 v3 = emb2[(size_t)r3 * D2 + c];
            float2 v4 = emb2[(size_t)r4 * D2 + c];
            float2 v5 = emb2[(size_t)r5 * D2 + c];
            float2 v6 = emb2[(size_t)r6 * D2 + c];
            float2 v7 = emb2[(size_t)r7 * D2 + c];
            s0 += ((v0.x + v1.x) + (v2.x + v3.x)) + ((v4.x + v5.x) + (v6.x + v7.x));
            s1 += ((v0.y + v1.y) + (v2.y + v3.y)) + ((v4.y + v5.y) + (v6.y + v7.y));
        }
        for (; i < n; ++i) {
            float2 v = emb2[(size_t)rows[i] * D2 + c];
            s0 += v.x; s1 += v.y;
        }
        const float iv = minv;
        float2 r; r.x = s0 * iv; r.y = s1 * iv;
        out2[(size_t)bs * D2 + c] = r;
    }

    // 2b: arg slots via flat entry list (CTA-uniform control flow, 4-way MLP)
    {
        const size_t OPRED2 = (size_t)Bc * Sc * D2;            // 196608
        const size_t OA2    = (size_t)Bc * Sc * Ac * D2;       // 1179648

        const int ne = nent_s;
        int   cur = -1;
        float ax = 0.f, ay = 0.f;

        auto flush = [&](int slot) {
            const int type = slot / Ac;
            const int a    = slot % Ac;
            const size_t ob = OPRED2 + (size_t)type * OA2 + ((size_t)bs * Ac + a) * D2;
            const float iv = sinv[slot];
            float2 r; r.x = ax * iv; r.y = ay * iv;
            out2[ob + c] = r;
        };

        int i = 0;
        for (; i + 4 <= ne; i += 4) {
            unsigned e0 = ent[i], e1 = ent[i + 1], e2e = ent[i + 2], e3 = ent[i + 3];
            float2 v0 = emb2[(size_t)(e0  & 0xFF) * D2 + c];
            float2 v1 = emb2[(size_t)(e1  & 0xFF) * D2 + c];
            float2 v2 = emb2[(size_t)(e2e & 0xFF) * D2 + c];
            float2 v3 = emb2[(size_t)(e3  & 0xFF) * D2 + c];
            unsigned es[4] = {e0, e1, e2e, e3};
            float2  vs[4] = {v0, v1, v2, v3};
            #pragma unroll
            for (int k = 0; k < 4; ++k) {
                int slot = (int)(es[k] >> 8);
                if (slot != cur) {
                    if (cur >= 0) flush(cur);
                    cur = slot; ax = vs[k].x; ay = vs[k].y;
                } else {
                    ax += vs[k].x; ay += vs[k].y;
                }
            }
        }
        for (; i < ne; ++i) {
            unsigned e = ent[i];
            float2 v = emb2[(size_t)(e & 0xFF) * D2 + c];
            int slot = (int)(e >> 8);
            if (slot != cur) {
                if (cur >= 0) flush(cur);
                cur = slot; ax = v.x; ay = v.y;
            } else {
                ax += v.x; ay += v.y;
            }
        }
        if (cur >= 0) flush(cur);

        // invalid slots -> zeros (d_out is poisoned, must write)
        #pragma unroll
        for (int slot = 0; slot < NSLOT; ++slot) {
            if (!svalid[slot]) {
                const int type = slot / Ac;
                const int a    = slot % Ac;
                const size_t ob = OPRED2 + (size_t)type * OA2 + ((size_t)bs * Ac + a) * D2;
                float2 z; z.x = 0.f; z.y = 0.f;
                out2[ob + c] = z;
            }
        }
    }
}

extern "C" void kernel_launch(void* const* d_in, const int* in_sizes, int n_in,
                              void* d_out, int out_size)
{
    const int*   sid  = (const int*)  d_in[0];
    const int*   mask = (const int*)  d_in[1];
    const float* emb  = (const float*)d_in[2];
    const int*   pred = (const int*)  d_in[3];
    const int*   arg0 = (const int*)  d_in[4];
    const int*   arg1 = (const int*)  d_in[5];
    float* out = (float*)d_out;

    dim3 grid(Bc * Sc, 2);
    srl_kernel<<<grid, TPB>>>(sid, mask, emb, pred, arg0, arg1, out);
}

// round 4
// speedup vs baseline: 1.6776x; 1.1491x over previous
#include <cuda_runtime.h>

// SRLEmbeddings: B=16,S=32,L=128,D=768,A=6,M=10
// Two-kernel design:
//   prep_kernel:   warp-per-(b,s) computes mask row list + arg slot entry list
//                  into a global descriptor (all the ballot/latency-serial work).
//   stream_kernel: pure float2 streaming, no smem/sync, grid (512,3) x 128.

#define Bc 16
#define Sc 32
#define Lc 128
#define Dc 768
#define D2 384          // float2 per row
#define Ac 6
#define Mc 10
#define NSLOT 18        // 3 arg types * A
#define NBS (Bc * Sc)   // 512
#define ENTCAP (NSLOT * Lc)   // absolute worst case

struct __align__(16) SlotDesc {
    int      nrows;            // 0
    int      nent;             // 4
    unsigned svalid;           // 8
    float    minv;             // 12
    float    sinv[NSLOT];      // 16..88
    unsigned char pad[8];      // ..96
    unsigned char rows[Lc];    // 96..224 (8-aligned)
    unsigned short ent[ENTCAP];// 224.. (row | slot<<8), slot-ordered
};

__device__ SlotDesc g_desc[NBS];

// ---------------------------------------------------------------------------
// Kernel 1: per-(b,s) descriptor build. One warp per bs, 8 warps per CTA.
// ---------------------------------------------------------------------------
__global__ __launch_bounds__(256, 4)
void prep_kernel(const int* __restrict__ sid_g,
                 const int* __restrict__ mask_g,
                 const int* __restrict__ pred_g,
                 const int* __restrict__ arg0_g,
                 const int* __restrict__ arg1_g)
{
    const unsigned FULL = 0xFFFFFFFFu;
    const int wid  = threadIdx.x >> 5;
    const int lane = threadIdx.x & 31;
    const int bs   = blockIdx.x * 8 + wid;
    SlotDesc* d = &g_desc[bs];

    // sentence ids in 4 regs per lane (one batched round of loads)
    const int sb = bs * Lc;
    int s0 = sid_g[sb + lane];
    int s1 = sid_g[sb + lane + 32];
    int s2 = sid_g[sb + lane + 64];
    int s3 = sid_g[sb + lane + 96];

    // mask bitmap
    int m0 = mask_g[sb + lane];
    int m1 = mask_g[sb + lane + 32];
    int m2 = mask_g[sb + lane + 64];
    int m3 = mask_g[sb + lane + 96];

    // token prefetch: 60 ints per type, 2 regs each (batched loads)
    const int tb = bs * Ac * Mc;  // *60
    int p0 = pred_g[tb + lane];
    int p1 = (lane < 28) ? pred_g[tb + 32 + lane] : 0;
    int q0 = arg0_g[tb + lane];
    int q1 = (lane < 28) ? arg0_g[tb + 32 + lane] : 0;
    int r0 = arg1_g[tb + lane];
    int r1 = (lane < 28) ? arg1_g[tb + 32 + lane] : 0;

    unsigned mb[4];
    mb[0] = __ballot_sync(FULL, m0 != 0);
    mb[1] = __ballot_sync(FULL, m1 != 0);
    mb[2] = __ballot_sync(FULL, m2 != 0);
    mb[3] = __ballot_sync(FULL, m3 != 0);

    // mask row list
    {
        int off = 0;
        #pragma unroll
        for (int w = 0; w < 4; ++w) {
            if (mb[w] & (1u << lane)) {
                int rank = __popc(mb[w] & ((1u << lane) - 1u));
                d->rows[off + rank] = (unsigned char)(w * 32 + lane);
            }
            off += __popc(mb[w]);
        }
        if (lane == 0) { d->nrows = off; d->minv = 1.0f / (float)max(off, 1); }
    }

    // arg slots: last m (highest) with token!=0 and >=1 match wins
    int nent = 0;
    unsigned svalid = 0;
    #pragma unroll
    for (int slot = 0; slot < NSLOT; ++slot) {
        const int type = slot / Ac;
        const int a    = slot % Ac;
        for (int m = Mc - 1; m >= 0; --m) {
            const int i = a * Mc + m;            // 0..59, uniform
            int src;
            if (type == 0)      src = (i < 32) ? p0 : p1;
            else if (type == 1) src = (i < 32) ? q0 : q1;
            else                src = (i < 32) ? r0 : r1;
            int tok = __shfl_sync(FULL, src, i & 31);
            if (tok == 0) continue;
            unsigned c0 = __ballot_sync(FULL, s0 == tok);
            unsigned c1 = __ballot_sync(FULL, s1 == tok);
            unsigned c2 = __ballot_sync(FULL, s2 == tok);
            unsigned c3 = __ballot_sync(FULL, s3 == tok);
            int cnt = __popc(c0) + __popc(c1) + __popc(c2) + __popc(c3);
            if (cnt > 0) {
                svalid |= 1u << slot;
                if (lane == 0) d->sinv[slot] = 1.0f / (float)cnt;
                unsigned cw[4] = {c0, c1, c2, c3};
                int off = nent;
                #pragma unroll
                for (int w = 0; w < 4; ++w) {
                    if (cw[w] & (1u << lane)) {
                        int rank = __popc(cw[w] & ((1u << lane) - 1u));
                        d->ent[off + rank] =
                            (unsigned short)((w * 32 + lane) | (slot << 8));
                    }
                    off += __popc(cw[w]);
                }
                nent = off;
                break;
            }
        }
    }
    if (lane == 0) { d->nent = nent; d->svalid = svalid; }
}

// ---------------------------------------------------------------------------
// Kernel 2: pure streaming. grid (512, 3), block 128, 1 float2 per thread.
// ---------------------------------------------------------------------------
__global__ __launch_bounds__(128, 12)
void stream_kernel(const float* __restrict__ emb_g,
                   float*       __restrict__ out)
{
    const int bs  = blockIdx.x;
    const int tid = threadIdx.x;
    const SlotDesc* __restrict__ d = &g_desc[bs];

    // header: one 16B uniform load
    const int4 hdr = *(const int4*)d;
    const int      nrows  = hdr.x;
    const int      nent   = hdr.y;
    const unsigned svalid = (unsigned)hdr.z;
    const float    minv   = __int_as_float(hdr.w);

    const float2* __restrict__ emb2 =
        (const float2*)(emb_g + (size_t)bs * Lc * Dc);     // row stride D2
    float2* out2 = (float2*)out;
    const int c = blockIdx.y * 128 + tid;                   // float2 column

    // ---- masked mean: 8 independent LDG.64 in flight ----
    {
        float sx = 0.f, sy = 0.f;
        int i = 0;
        for (; i + 8 <= nrows; i += 8) {
            uint2 rw = *(const uint2*)&d->rows[i];          // 8-aligned
            unsigned ra = rw.x, rb = rw.y;
            float2 v0 = emb2[(size_t)( ra        & 0xFF) * D2 + c];
            float2 v1 = emb2[(size_t)((ra >>  8) & 0xFF) * D2 + c];
            float2 v2 = emb2[(size_t)((ra >> 16) & 0xFF) * D2 + c];
            float2 v3 = emb2[(size_t)((ra >> 24) & 0xFF) * D2 + c];
            float2 v4 = emb2[(size_t)( rb        & 0xFF) * D2 + c];
            float2 v5 = emb2[(size_t)((rb >>  8) & 0xFF) * D2 + c];
            float2 v6 = emb2[(size_t)((rb >> 16) & 0xFF) * D2 + c];
            float2 v7 = emb2[(size_t)((rb >> 24) & 0xFF) * D2 + c];
            sx += ((v0.x + v1.x) + (v2.x + v3.x)) + ((v4.x + v5.x) + (v6.x + v7.x));
            sy += ((v0.y + v1.y) + (v2.y + v3.y)) + ((v4.y + v5.y) + (v6.y + v7.y));
        }
        for (; i < nrows; ++i) {
            float2 v = emb2[(size_t)d->rows[i] * D2 + c];
            sx += v.x; sy += v.y;
        }
        float2 r; r.x = sx * minv; r.y = sy * minv;
        __stcs(&out2[(size_t)bs * D2 + c], r);
    }

    // ---- arg slots: flat entry list, 4-way MLP, running-slot accumulator ----
    {
        const size_t OPRED2 = (size_t)NBS * D2;             // 196608
        const size_t OA2    = (size_t)NBS * Ac * D2;        // 1179648

        int   cur = -1;
        float ax = 0.f, ay = 0.f;

        auto flush = [&](int slot) {
            const int type = slot / Ac;
            const int a    = slot % Ac;
            const size_t ob = OPRED2 + (size_t)type * OA2 + ((size_t)bs * Ac + a) * D2;
            const float iv = d->sinv[slot];
            float2 r; r.x = ax * iv; r.y = ay * iv;
            __stcs(&out2[ob + c], r);
        };

        int i = 0;
        for (; i + 4 <= nent; i += 4) {
            unsigned e0 = d->ent[i],     e1 = d->ent[i + 1];
            unsigned e2 = d->ent[i + 2], e3 = d->ent[i + 3];
            float2 v0 = emb2[(size_t)(e0 & 0xFF) * D2 + c];
            float2 v1 = emb2[(size_t)(e1 & 0xFF) * D2 + c];
            float2 v2 = emb2[(size_t)(e2 & 0xFF) * D2 + c];
            float2 v3 = emb2[(size_t)(e3 & 0xFF) * D2 + c];
            unsigned es[4] = {e0, e1, e2, e3};
            float2  vs[4] = {v0, v1, v2, v3};
            #pragma unroll
            for (int k = 0; k < 4; ++k) {
                int slot = (int)(es[k] >> 8);
                if (slot != cur) {
                    if (cur >= 0) flush(cur);
                    cur = slot; ax = vs[k].x; ay = vs[k].y;
                } else {
                    ax += vs[k].x; ay += vs[k].y;
                }
            }
        }
        for (; i < nent; ++i) {
            unsigned e = d->ent[i];
            float2 v = emb2[(size_t)(e & 0xFF) * D2 + c];
            int slot = (int)(e >> 8);
            if (slot != cur) {
                if (cur >= 0) flush(cur);
                cur = slot; ax = v.x; ay = v.y;
            } else {
                ax += v.x; ay += v.y;
            }
        }
        if (cur >= 0) flush(cur);

        // invalid slots -> zeros (d_out is poisoned, must write)
        #pragma unroll
        for (int slot = 0; slot < NSLOT; ++slot) {
            if (!((svalid >> slot) & 1u)) {
                const int type = slot / Ac;
                const int a    = slot % Ac;
                const size_t ob = OPRED2 + (size_t)type * OA2 + ((size_t)bs * Ac + a) * D2;
                float2 z; z.x = 0.f; z.y = 0.f;
                __stcs(&out2[ob + c], z);
            }
        }
    }
}

extern "C" void kernel_launch(void* const* d_in, const int* in_sizes, int n_in,
                              void* d_out, int out_size)
{
    const int*   sid  = (const int*)  d_in[0];
    const int*   mask = (const int*)  d_in[1];
    const float* emb  = (const float*)d_in[2];
    const int*   pred = (const int*)  d_in[3];
    const int*   arg0 = (const int*)  d_in[4];
    const int*   arg1 = (const int*)  d_in[5];
    float* out = (float*)d_out;

    prep_kernel<<<NBS / 8, 256>>>(sid, mask, pred, arg0, arg1);
    dim3 grid(NBS, 3);
    stream_kernel<<<grid, 128>>>(emb, out);
}